// round 8
// baseline (speedup 1.0000x reference)
#include <cuda_runtime.h>

// ---------------------------------------------------------------------------
// Leaky CTRNN persistent scan, v5. B=64, T=512, D_IN=256, H=1024, D_OUT=256
//
//  k2: rnn_persistent — 147 blocks x 512 thr (1/SM, co-resident), 514 phases:
//       role r = bid/49 in {0,1,2}; block j = bid%49 owns cols
//       [(1024 j)/49, (1024(j+1))/49)  (20-21 cols, padded to 24 in smem).
//       role0: fr0(p)   = relu(v0=.9v0+.1(fr0(p-1)@Wrec0^T + xin0))
//       role1: pin(p-1) = fr0(p-1)@Win1^T + b1
//       role2: fr1(p-2) = relu(v1=.9v1+.1(fr1(p-3)@Wrec1^T + pin))
//      Weights persist in smem (zero-padded). A staged per 128-k chunk via
//      cp.async.bulk + mbarrier, double-buffered. Split-K x8, microtile
//      8 batches x 3 cols, packed fma.rn.f32x2 ordered for .reuse.
//      Strided d_out stores deferred past barrier arrival.
// ---------------------------------------------------------------------------

namespace {
constexpr int B = 64, T = 512, DIN = 256, H = 1024, DOUT = 256;
constexpr float AL = 0.1f, OMA = 0.9f;

constexpr int NBR   = 49;            // blocks per role
constexpr int NBLK  = 3 * NBR;       // 147
constexpr int THR   = 512;
constexpr int NCOLP = 24;            // padded col count per block
constexpr int KC    = 128;           // k-chunk staged in smem
constexpr int NCH   = H / KC;        // 8
constexpr int HB    = H * B;
constexpr int ABUF  = 2 * KC * B;    // floats (64KB), reused for reduce
constexpr int CBYTES = KC * B * 4;   // 32768
constexpr int MBAR_OFF = (ABUF + H * NCOLP) * 4;   // 64KB + 96KB
constexpr int SMEM_P   = MBAR_OFF + 16;
}

// Scratch (__device__ globals: allocation-free rule)
__device__ float g_xin0[(size_t)T * H * B];   // [t][h][b]
__device__ float g_s0f[(size_t)T * H * B];    // fr0 history [t][h][b]
__device__ float g_s1f[(size_t)T * H * B];    // fr1 history [t][h][b]
__device__ float g_pin[2 * (size_t)H * B];    // [t&1][h][b]
__device__ volatile unsigned g_gen;
__device__ unsigned g_cnt;

// ---- helpers ---------------------------------------------------------------
__device__ __forceinline__ unsigned long long dup2(float x) {
    unsigned long long d;
    asm("mov.b64 %0, {%1, %1};" : "=l"(d) : "r"(__float_as_uint(x)));
    return d;
}
__device__ __forceinline__ void fma2(unsigned long long& a,
                                     unsigned long long x, unsigned long long y) {
    asm("fma.rn.f32x2 %0, %1, %2, %0;" : "+l"(a) : "l"(x), "l"(y));
}
__device__ __forceinline__ void mbar_init(unsigned mbar, unsigned count) {
    asm volatile("mbarrier.init.shared.b64 [%0], %1;" :: "r"(mbar), "r"(count)
                 : "memory");
}
__device__ __forceinline__ void mbar_expect_tx(unsigned mbar, unsigned bytes) {
    asm volatile("mbarrier.arrive.expect_tx.shared.b64 _, [%0], %1;"
                 :: "r"(mbar), "r"(bytes) : "memory");
}
__device__ __forceinline__ void bulk_g2s(unsigned dst, const float* src,
                                         unsigned bytes, unsigned mbar) {
    asm volatile(
        "cp.async.bulk.shared::cta.global.mbarrier::complete_tx::bytes "
        "[%0], [%1], %2, [%3];"
        :: "r"(dst), "l"(src), "r"(bytes), "r"(mbar) : "memory");
}
__device__ __forceinline__ void mbar_wait(unsigned mbar, unsigned parity) {
    asm volatile(
        "{\n\t"
        ".reg .pred P;\n\t"
        "LAB_%=:\n\t"
        "mbarrier.try_wait.parity.shared.b64 P, [%0], %1;\n\t"
        "@!P bra LAB_%=;\n\t"
        "}\n"
        :: "r"(mbar), "r"(parity) : "memory");
}

// ---------------------------------------------------------------------------
__global__ void __launch_bounds__(THR, 1)
rnn_persistent(const float* __restrict__ Wrec0, const float* __restrict__ Win1,
               const float* __restrict__ Wrec1, const float* __restrict__ b1,
               float* __restrict__ states0, float* __restrict__ states1)
{
    extern __shared__ float sm[];
    float* aS = sm;                  // [2][KC][B], reused as reduce scratch
    float* wS = sm + ABUF;           // [H][NCOLP] k-major, zero-padded

    const unsigned sbase = (unsigned)__cvta_generic_to_shared(sm);
    const unsigned mb0 = sbase + MBAR_OFF;
    const unsigned mb1 = sbase + MBAR_OFF + 8;
    const unsigned abuf0 = sbase;
    const unsigned abuf1 = sbase + CBYTES;

    const int tid  = threadIdx.x;
    const int role = (int)blockIdx.x / NBR;
    const int j    = (int)blockIdx.x - role * NBR;
    const int n0   = (j * H) / NBR;
    const int n1   = ((j + 1) * H) / NBR;
    const int ncol = n1 - n0;            // 20 or 21

    // split-K slice / microtile mapping
    const int kt     = tid >> 6;         // k-slice 0..7
    const int tl     = tid & 63;
    const int bgroup = tl & 7;           // 8 batches -> bbase = bgroup*8
    const int cgroup = tl >> 3;          // 3 cols    -> cbase = cgroup*3
    const int bbase  = bgroup * 8;
    const int cbase  = cgroup * 3;

    // One-time weight load: wS[k][n] = W[n0+n][k], zero for n >= ncol
    const float* Wsrc = role == 0 ? Wrec0 : (role == 1 ? Win1 : Wrec1);
    for (int it = tid; it < NCOLP * (H / 4); it += THR) {
        int n  = it % NCOLP;
        int k4 = (it / NCOLP) * 4;
        float4 w = make_float4(0.f, 0.f, 0.f, 0.f);
        if (n < ncol) w = *(const float4*)(Wsrc + (size_t)(n0 + n) * H + k4);
        wS[(k4 + 0) * NCOLP + n] = w.x; wS[(k4 + 1) * NCOLP + n] = w.y;
        wS[(k4 + 2) * NCOLP + n] = w.z; wS[(k4 + 3) * NCOLP + n] = w.w;
    }
    // epilogue mapping: 4 contiguous batches of one col per thread
    const int en = tid >> 4;             // local col 0..31 (active if < ncol)
    const int eb = (tid & 15) * 4;       // batch base 0..60
    const bool ecol = (en < ncol);
    const float b1v = (role == 1 && ecol) ? b1[n0 + en] : 0.f;

    if (tid == 0) { mbar_init(mb0, 1); mbar_init(mb1, 1); }
    asm volatile("fence.proxy.async.shared::cta;" ::: "memory");
    __syncthreads();

    unsigned par0 = 0, par1 = 0;
    float v[4] = {0.f, 0.f, 0.f, 0.f};

    for (int p = 0; p < T + 2; p++) {
        int t; const float* asrc = nullptr; bool act, dogemm;
        if (role == 0) {
            t = p; act = (t < T); dogemm = act && (p > 0);
            if (dogemm) asrc = g_s0f + (size_t)(p - 1) * HB;
        } else if (role == 1) {
            t = p - 1; act = (t >= 0 && t < T); dogemm = act;
            if (dogemm) asrc = g_s0f + (size_t)t * HB;
        } else {
            t = p - 2; act = (t >= 0 && t < T); dogemm = act && (t > 0);
            if (dogemm) asrc = g_s1f + (size_t)(t - 1) * HB;
        }

        // acc[col 0..2][batch-pair 0..3]
        unsigned long long acc[3][4];
        #pragma unroll
        for (int c2 = 0; c2 < 3; c2++)
            #pragma unroll
            for (int q = 0; q < 4; q++) acc[c2][q] = 0ull;

        if (dogemm) {
            if (tid == 0) {                       // prefetch chunk 0
                mbar_expect_tx(mb0, CBYTES);
                bulk_g2s(abuf0, asrc, CBYTES, mb0);
            }
            for (int c = 0; c < NCH; c++) {
                if (c + 1 < NCH && tid == 0) {    // prefetch chunk c+1
                    unsigned dst = ((c + 1) & 1) ? abuf1 : abuf0;
                    unsigned mbn = ((c + 1) & 1) ? mb1 : mb0;
                    mbar_expect_tx(mbn, CBYTES);
                    bulk_g2s(dst, asrc + (size_t)(c + 1) * KC * B, CBYTES, mbn);
                }
                if (c & 1) { mbar_wait(mb1, par1); par1 ^= 1; }
                else       { mbar_wait(mb0, par0); par0 ^= 1; }

                const float* ab = aS + (c & 1) * (KC * B) + (kt * 16) * B + bbase;
                const float* wb = wS + (c * KC + kt * 16) * NCOLP + cbase;
                #pragma unroll
                for (int kk = 0; kk < 16; kk++) {
                    ulonglong2 A0 = *(const ulonglong2*)(ab + kk * B);      // b..b+3
                    ulonglong2 A1 = *(const ulonglong2*)(ab + kk * B + 4);  // b+4..b+7
                    unsigned long long w0 = dup2(wb[kk * NCOLP + 0]);
                    unsigned long long w1 = dup2(wb[kk * NCOLP + 1]);
                    unsigned long long w2 = dup2(wb[kk * NCOLP + 2]);
                    // ordered so consecutive FFMA2 share the A operand (.reuse)
                    fma2(acc[0][0], A0.x, w0); fma2(acc[1][0], A0.x, w1);
                    fma2(acc[2][0], A0.x, w2);
                    fma2(acc[0][1], A0.y, w0); fma2(acc[1][1], A0.y, w1);
                    fma2(acc[2][1], A0.y, w2);
                    fma2(acc[0][2], A1.x, w0); fma2(acc[1][2], A1.x, w1);
                    fma2(acc[2][2], A1.x, w2);
                    fma2(acc[0][3], A1.y, w0); fma2(acc[1][3], A1.y, w1);
                    fma2(acc[2][3], A1.y, w2);
                }
                __syncthreads();   // all reads of this buffer done
            }
        }

        float fr[4];
        bool havefr = false;

        if (act) {
            // split-K partials -> smem: red[n][kt][pair]
            unsigned long long* red = (unsigned long long*)aS;
            #pragma unroll
            for (int c2 = 0; c2 < 3; c2++)
                #pragma unroll
                for (int q = 0; q < 4; q++)
                    red[(cbase + c2) * 256 + kt * 32 + bgroup * 4 + q] = acc[c2][q];
            __syncthreads();

            if (ecol) {
                float4 s = make_float4(0.f, 0.f, 0.f, 0.f);
                #pragma unroll
                for (int q = 0; q < 8; q++) {
                    float4 pz = *(const float4*)&aS[en * 512 + q * 64 + eb];
                    s.x += pz.x; s.y += pz.y; s.z += pz.z; s.w += pz.w;
                }
                const size_t vo = ((size_t)t * H + n0 + en) * B + eb;
                if (role == 1) {
                    float4 o = make_float4(s.x + b1v, s.y + b1v,
                                           s.z + b1v, s.w + b1v);
                    *(float4*)&g_pin[(size_t)(t & 1) * HB +
                                     (size_t)(n0 + en) * B + eb] = o;
                } else {
                    float4 add;
                    if (role == 0)
                        add = *(const float4*)&g_xin0[vo];
                    else
                        add = __ldcg((const float4*)&g_pin[(size_t)(t & 1) * HB +
                                                           (size_t)(n0 + en) * B + eb]);
                    v[0] = OMA * v[0] + AL * (s.x + add.x);
                    v[1] = OMA * v[1] + AL * (s.y + add.y);
                    v[2] = OMA * v[2] + AL * (s.z + add.z);
                    v[3] = OMA * v[3] + AL * (s.w + add.w);
                    fr[0] = fmaxf(v[0], 0.f); fr[1] = fmaxf(v[1], 0.f);
                    fr[2] = fmaxf(v[2], 0.f); fr[3] = fmaxf(v[3], 0.f);
                    havefr = true;
                    float* dst = (role == 0) ? g_s0f : g_s1f;
                    *(float4*)&dst[vo] = make_float4(fr[0], fr[1], fr[2], fr[3]);
                }
            }
        }

        if (p < T + 1) {
            // -- grid barrier, arrival first; strided d_out stores hidden under wait
            __syncthreads();
            unsigned gen;
            if (tid == 0) {
                __threadfence();
                gen = g_gen;
                if (atomicAdd(&g_cnt, 1u) == NBLK - 1) {
                    g_cnt = 0;
                    __threadfence();
                    g_gen = gen + 1;
                }
            }
            if (havefr) {   // d_out states store (not consumed in-kernel)
                float* st = (role == 0) ? states0 : states1;
                #pragma unroll
                for (int bl = 0; bl < 4; bl++)
                    st[((size_t)(eb + bl) * T + t) * H + n0 + en] = fr[bl];
            }
            if (tid == 0) {
                while (g_gen == gen) {}
                __threadfence();
            }
            __syncthreads();
        } else if (havefr) {   // last phase: just store
            float* st = (role == 0) ? states0 : states1;
            #pragma unroll
            for (int bl = 0; bl < 4; bl++)
                st[((size_t)(eb + bl) * T + t) * H + n0 + en] = fr[bl];
        }
    }
}

// ---------------------------------------------------------------------------
// gemm_in0: per timestep t, xin0[t][h][b] = W_in0[h,:] . x[b,t,:] + b0[h]
// ---------------------------------------------------------------------------
__global__ void __launch_bounds__(256)
gemm_in0_kernel(const float* __restrict__ x,
                const float* __restrict__ Win0,
                const float* __restrict__ b0)
{
    __shared__ float aS[16 * 64];
    __shared__ float bS[16 * 64];
    const int tid = threadIdx.x;
    const int m0 = blockIdx.x * 64;
    const int t  = blockIdx.y;
    const int lr = tid >> 2;
    const int lk = (tid & 3) * 4;
    const int tm4 = (tid >> 4) * 4;
    const int tn4 = (tid & 15) * 4;
    float acc[4][4] = {};
    const float* ap = Win0 + (size_t)(m0 + lr) * DIN + lk;
    const float* bp = x + ((size_t)lr * T + t) * DIN + lk;

    for (int k0 = 0; k0 < DIN; k0 += 16) {
        float4 av = *(const float4*)(ap + k0);
        float4 bv = *(const float4*)(bp + k0);
        __syncthreads();
        aS[(lk + 0) * 64 + lr] = av.x; aS[(lk + 1) * 64 + lr] = av.y;
        aS[(lk + 2) * 64 + lr] = av.z; aS[(lk + 3) * 64 + lr] = av.w;
        bS[(lk + 0) * 64 + lr] = bv.x; bS[(lk + 1) * 64 + lr] = bv.y;
        bS[(lk + 2) * 64 + lr] = bv.z; bS[(lk + 3) * 64 + lr] = bv.w;
        __syncthreads();
        #pragma unroll
        for (int kk = 0; kk < 16; kk++) {
            float4 a = *(const float4*)&aS[kk * 64 + tm4];
            float4 b = *(const float4*)&bS[kk * 64 + tn4];
            acc[0][0] += a.x * b.x; acc[0][1] += a.x * b.y;
            acc[0][2] += a.x * b.z; acc[0][3] += a.x * b.w;
            acc[1][0] += a.y * b.x; acc[1][1] += a.y * b.y;
            acc[1][2] += a.y * b.z; acc[1][3] += a.y * b.w;
            acc[2][0] += a.z * b.x; acc[2][1] += a.z * b.y;
            acc[2][2] += a.z * b.z; acc[2][3] += a.z * b.w;
            acc[3][0] += a.w * b.x; acc[3][1] += a.w * b.y;
            acc[3][2] += a.w * b.z; acc[3][3] += a.w * b.w;
        }
    }
    #pragma unroll
    for (int i = 0; i < 4; i++) {
        float bb = b0[m0 + tm4 + i];
        float4 o = make_float4(acc[i][0] + bb, acc[i][1] + bb,
                               acc[i][2] + bb, acc[i][3] + bb);
        *(float4*)&g_xin0[((size_t)t * H + m0 + tm4 + i) * B + tn4] = o;
    }
}

// ---------------------------------------------------------------------------
// gemm_out: output[B*T, DOUT] = states1[B*T, H] @ W_out^T + b_out
// ---------------------------------------------------------------------------
__global__ void __launch_bounds__(256)
gemm_out_kernel(const float* __restrict__ states1,
                const float* __restrict__ Wout,
                const float* __restrict__ bout,
                float* __restrict__ out)
{
    __shared__ float aS[16 * 64];
    __shared__ float bS[16 * 64];
    const int tid = threadIdx.x;
    const int m0 = blockIdx.x * 64;
    const int n0 = blockIdx.y * 64;
    const int lr = tid >> 2;
    const int lk = (tid & 3) * 4;
    const int tm4 = (tid >> 4) * 4;
    const int tn4 = (tid & 15) * 4;
    float acc[4][4] = {};
    const float* ap = states1 + (size_t)(m0 + lr) * H + lk;
    const float* bp = Wout    + (size_t)(n0 + lr) * H + lk;

    for (int k0 = 0; k0 < H; k0 += 16) {
        float4 av = *(const float4*)(ap + k0);
        float4 bv = *(const float4*)(bp + k0);
        __syncthreads();
        aS[(lk + 0) * 64 + lr] = av.x; aS[(lk + 1) * 64 + lr] = av.y;
        aS[(lk + 2) * 64 + lr] = av.z; aS[(lk + 3) * 64 + lr] = av.w;
        bS[(lk + 0) * 64 + lr] = bv.x; bS[(lk + 1) * 64 + lr] = bv.y;
        bS[(lk + 2) * 64 + lr] = bv.z; bS[(lk + 3) * 64 + lr] = bv.w;
        __syncthreads();
        #pragma unroll
        for (int kk = 0; kk < 16; kk++) {
            float4 a = *(const float4*)&aS[kk * 64 + tm4];
            float4 b = *(const float4*)&bS[kk * 64 + tn4];
            acc[0][0] += a.x * b.x; acc[0][1] += a.x * b.y;
            acc[0][2] += a.x * b.z; acc[0][3] += a.x * b.w;
            acc[1][0] += a.y * b.x; acc[1][1] += a.y * b.y;
            acc[1][2] += a.y * b.z; acc[1][3] += a.y * b.w;
            acc[2][0] += a.z * b.x; acc[2][1] += a.z * b.y;
            acc[2][2] += a.z * b.z; acc[2][3] += a.z * b.w;
            acc[3][0] += a.w * b.x; acc[3][1] += a.w * b.y;
            acc[3][2] += a.w * b.z; acc[3][3] += a.w * b.w;
        }
    }
    #pragma unroll
    for (int i = 0; i < 4; i++) {
        float4 bb = *(const float4*)&bout[n0 + tn4];
        int gm = m0 + tm4 + i;
        float4 o = make_float4(acc[i][0] + bb.x, acc[i][1] + bb.y,
                               acc[i][2] + bb.z, acc[i][3] + bb.w);
        *(float4*)&out[(size_t)gm * DOUT + n0 + tn4] = o;
    }
}

// ---------------------------------------------------------------------------
extern "C" void kernel_launch(void* const* d_in, const int* in_sizes, int n_in,
                              void* d_out, int out_size)
{
    (void)in_sizes; (void)n_in; (void)out_size;
    const float* x     = (const float*)d_in[0];
    const float* Win0  = (const float*)d_in[1];
    const float* Wrec0 = (const float*)d_in[2];
    const float* b0    = (const float*)d_in[3];
    const float* Win1  = (const float*)d_in[4];
    const float* Wrec1 = (const float*)d_in[5];
    const float* b1    = (const float*)d_in[6];
    const float* Wout  = (const float*)d_in[7];
    const float* bout  = (const float*)d_in[8];

    float* out     = (float*)d_out;                   // [B][T][DOUT]
    float* states0 = out + (size_t)B * T * DOUT;      // [B][T][H]
    float* states1 = states0 + (size_t)B * T * H;     // [B][T][H]

    cudaFuncSetAttribute(rnn_persistent,
                         cudaFuncAttributeMaxDynamicSharedMemorySize, SMEM_P);

    gemm_in0_kernel<<<dim3(H / 64, T), 256>>>(x, Win0, b0);
    rnn_persistent<<<NBLK, THR, SMEM_P>>>(Wrec0, Win1, Wrec1, b1,
                                          states0, states1);
    gemm_out_kernel<<<dim3((B * T) / 64, DOUT / 64), 256>>>(states1, Wout,
                                                            bout, out);
}